// round 6
// baseline (speedup 1.0000x reference)
#include <cuda_runtime.h>
#include <math.h>

#define H 1024
#define VOCAB 50257
#define NB 148                  // persistent: one block per SM
#define NT 512
#define NWARPS (NB * 16)        // 2368 warps
#define PIN_ROWS 16384          // first 64MB of W_out: evict_last
#define FIN_CHUNK 340           // ceil(VOCAB / NB)

// Scratch (__device__ globals — allocation-free rule)
__device__ float g_partA[8192];     // layer1 partials: [0,4096)=Wih, [4096,8192)=Whh
__device__ float g_partB[8192];     // layer2 partials
__device__ float2 g_pairs[NB];
__device__ unsigned g_cnt[4];
__device__ volatile unsigned g_gen[4];

// ---------------------------------------------------------------------------
__device__ __forceinline__ float sigmoidf_fast(float x) {
    return 1.f / (1.f + __expf(-x));
}

__device__ __forceinline__ void merge_pair(float& m, float& s, float m2, float s2) {
    if (m2 > m) { float t = s; s = s2 + t * __expf(m - m2); m = m2; }
    else if (m2 != -INFINITY) { s += s2 * __expf(m2 - m); }
}

// Grid-wide spin barrier (all NB blocks co-resident; gen monotonic across replays)
__device__ __forceinline__ void gsync(int b) {
    __syncthreads();
    if (threadIdx.x == 0) {
        __threadfence();
        unsigned cur = g_gen[b];
        unsigned pos = atomicAdd(&g_cnt[b], 1u);
        if (pos == NB - 1) {
            g_cnt[b] = 0;
            __threadfence();
            g_gen[b] = cur + 1;
        } else {
            while (g_gen[b] == cur) __nanosleep(32);
        }
        __threadfence();
    }
    __syncthreads();
}

// 256-bit loads with L2 eviction policy (sm_103a: hints need .v4.b64)
struct f8 { float4 a, b; };

__device__ __forceinline__ f8 ld8_evict_last(const float* p) {
    f8 v;
    asm volatile(
        "{\n\t.reg .b64 q0,q1,q2,q3;\n\t"
        "ld.global.nc.L2::evict_last.v4.b64 {q0,q1,q2,q3}, [%8];\n\t"
        "mov.b64 {%0,%1}, q0;\n\tmov.b64 {%2,%3}, q1;\n\t"
        "mov.b64 {%4,%5}, q2;\n\tmov.b64 {%6,%7}, q3;\n\t}"
        : "=f"(v.a.x), "=f"(v.a.y), "=f"(v.a.z), "=f"(v.a.w),
          "=f"(v.b.x), "=f"(v.b.y), "=f"(v.b.z), "=f"(v.b.w)
        : "l"(p));
    return v;
}

__device__ __forceinline__ f8 ld8_evict_first(const float* p) {
    f8 v;
    asm volatile(
        "{\n\t.reg .b64 q0,q1,q2,q3;\n\t"
        "ld.global.nc.L2::evict_first.v4.b64 {q0,q1,q2,q3}, [%8];\n\t"
        "mov.b64 {%0,%1}, q0;\n\tmov.b64 {%2,%3}, q1;\n\t"
        "mov.b64 {%4,%5}, q2;\n\tmov.b64 {%6,%7}, q3;\n\t}"
        : "=f"(v.a.x), "=f"(v.a.y), "=f"(v.a.z), "=f"(v.a.w),
          "=f"(v.b.x), "=f"(v.b.y), "=f"(v.b.z), "=f"(v.b.w)
        : "l"(p));
    return v;
}

__device__ __forceinline__ float dot8(const f8& w, const float4& x0, const float4& x1) {
    return w.a.x * x0.x + w.a.y * x0.y + w.a.z * x0.z + w.a.w * x0.w
         + w.b.x * x1.x + w.b.y * x1.y + w.b.z * x1.z + w.b.w * x1.w;
}

__device__ __forceinline__ void row_load_last(const float* W, int lane, f8 w[4]) {
#pragma unroll
    for (int k = 0; k < 4; k++) w[k] = ld8_evict_last(W + (k * 32 + lane) * 8);
}
__device__ __forceinline__ void row_load_first(const float* W, int lane, f8 w[4]) {
#pragma unroll
    for (int k = 0; k < 4; k++) w[k] = ld8_evict_first(W + (k * 32 + lane) * 8);
}
__device__ __forceinline__ float row_dot(const f8 w[4], const float4* v4, int lane) {
    float acc = 0.f;
#pragma unroll
    for (int k = 0; k < 4; k++) {
        int c = (k * 32 + lane) * 2;
        acc += dot8(w[k], v4[c], v4[c + 1]);
    }
    return acc;
}

// LSTM elementwise for element j (torch gate order i, f, g, o)
__device__ __forceinline__ void act_phase(
        const float* __restrict__ part,
        const float* __restrict__ bih, const float* __restrict__ bhh,
        float cin, float& hout, float& cout, int j) {
    float gi = part[j]         + part[4096 + j]         + bih[j]         + bhh[j];
    float gf = part[j + H]     + part[4096 + j + H]     + bih[j + H]     + bhh[j + H];
    float gg = part[j + 2 * H] + part[4096 + j + 2 * H] + bih[j + 2 * H] + bhh[j + 2 * H];
    float go = part[j + 3 * H] + part[4096 + j + 3 * H] + bih[j + 3 * H] + bhh[j + 3 * H];
    cout = sigmoidf_fast(gf) * cin + sigmoidf_fast(gi) * tanhf(gg);
    hout = sigmoidf_fast(go) * tanhf(cout);
}

// ---------------------------------------------------------------------------
// Gates GEMV phase: 8192 virtual rows, 2 rows per step (8x256b in flight).
// vr < 4096: Wih vs sx (relu'd x).  vr >= 4096: Whh vs sh (h).
// Zero-source rows are skipped (no loads), partial written as 0.
// ---------------------------------------------------------------------------
__device__ __forceinline__ void gates_phase(
        const float* __restrict__ Wih, const float* __restrict__ Whh,
        const float4* sx4, const float4* sh4, float* __restrict__ part,
        int gw, int lane, bool x_zero, bool h_zero) {
#pragma unroll
    for (int k = 0; k < 2; k++) {
        int r0 = gw + 2 * k * NWARPS;
        int r1 = r0 + NWARPS;
        bool val1 = r1 < 8192;
        bool a0 = r0 < 4096, a1 = r1 < 4096;
        bool do0 = !(a0 ? x_zero : h_zero);
        bool do1 = val1 && !(a1 ? x_zero : h_zero);
        const float* W0 = (a0 ? Wih : Whh) + (long)(r0 & 4095) * H;
        const float* W1 = (a1 ? Wih : Whh) + (long)(r1 & 4095) * H;
        f8 w0[4], w1[4];
        if (do0) row_load_last(W0, lane, w0);
        if (do1) row_load_last(W1, lane, w1);
        float acc0 = do0 ? row_dot(w0, a0 ? sx4 : sh4, lane) : 0.f;
        float acc1 = do1 ? row_dot(w1, a1 ? sx4 : sh4, lane) : 0.f;
#pragma unroll
        for (int o = 16; o > 0; o >>= 1) {
            acc0 += __shfl_down_sync(0xffffffffu, acc0, o);
            acc1 += __shfl_down_sync(0xffffffffu, acc1, o);
        }
        if (lane == 0) {
            part[r0] = acc0;
            if (val1) part[r1] = acc1;
        }
    }
}

// ---------------------------------------------------------------------------
// ONE persistent kernel, 512 threads/block, 148 blocks, 3 grid barriers.
// ---------------------------------------------------------------------------
__global__ void __launch_bounds__(NT, 1) decoder_kernel(
        const int* __restrict__ id, const float* __restrict__ h0,
        const float* __restrict__ c0, const float* __restrict__ emb,
        const float* __restrict__ Wih, const float* __restrict__ Whh,
        const float* __restrict__ bih, const float* __restrict__ bhh,
        const float* __restrict__ Wout, const float* __restrict__ bout,
        float* __restrict__ out, int write_tail) {
    __shared__ float sx[H];
    __shared__ float sh[H];
    __shared__ float2 spair[16];
    __shared__ float s_lse;
    __shared__ int s_nzx, s_nzh;

    int t = threadIdx.x, lane = t & 31, warp = t >> 5;
    int gw = blockIdx.x * 16 + warp;
    const float4* sx4 = (const float4*)sx;
    const float4* sh4 = (const float4*)sh;

    // P0: stage relu(emb[id]) and h0; detect all-zero source vectors
    if (t == 0) { s_nzx = 0; s_nzh = 0; }
    __syncthreads();
    {
        const float* e = emb + (long)id[0] * H;
        float x0 = fmaxf(e[t], 0.f),       x1 = fmaxf(e[t + NT], 0.f);
        float hv0 = h0[t],                 hv1 = h0[t + NT];
        sx[t] = x0; sx[t + NT] = x1;
        sh[t] = hv0; sh[t + NT] = hv1;
        if (x0 != 0.f || x1 != 0.f) s_nzx = 1;
        if (hv0 != 0.f || hv1 != 0.f) s_nzh = 1;
    }
    __syncthreads();

    // P1: layer-1 gates GEMV
    gates_phase(Wih, Whh, sx4, sh4, g_partA, gw, lane, !s_nzx, !s_nzh);
    gsync(0);

    // P2: act1 — redundant per block; c1 stays in registers
    float h1a, c1a, h1b, c1b;
    act_phase(g_partA, bih, bhh, c0[t],      h1a, c1a, t);
    act_phase(g_partA, bih, bhh, c0[t + NT], h1b, c1b, t + NT);
    __syncthreads();
    if (t == 0) { s_nzx = 0; s_nzh = 0; }
    __syncthreads();
    {
        float x0 = fmaxf(h1a, 0.f), x1 = fmaxf(h1b, 0.f);
        sx[t] = x0; sx[t + NT] = x1;
        sh[t] = h1a; sh[t + NT] = h1b;
        if (x0 != 0.f || x1 != 0.f) s_nzx = 1;
        if (h1a != 0.f || h1b != 0.f) s_nzh = 1;
    }
    __syncthreads();

    // P3: layer-2 gates GEMV (same weights per reference)
    gates_phase(Wih, Whh, sx4, sh4, g_partB, gw, lane, !s_nzx, !s_nzh);
    gsync(1);

    // P4: act2 — redundant per block; block 0 writes the (h, c) tail
    float h2a, c2a, h2b, c2b;
    act_phase(g_partB, bih, bhh, c1a, h2a, c2a, t);
    act_phase(g_partB, bih, bhh, c1b, h2b, c2b, t + NT);
    __syncthreads();
    sx[t] = h2a; sx[t + NT] = h2b;
    if (write_tail && blockIdx.x == 0) {
        out[VOCAB + t]          = h2a;
        out[VOCAB + t + NT]     = h2b;
        out[VOCAB + H + t]      = c2a;
        out[VOCAB + H + t + NT] = c2b;
    }
    __syncthreads();

    // P5: logits GEMV, 2 rows/step, + per-warp online (max, sumexp)
    float m = -INFINITY, s = 0.f;
#pragma unroll
    for (int k = 0; k < 11; k++) {
        int r0 = gw + 2 * k * NWARPS;
        int r1 = r0 + NWARPS;
        bool v0 = r0 < VOCAB, v1 = r1 < VOCAB;
        f8 w0[4], w1[4];
        if (v0) {
            const float* p = Wout + (long)r0 * H;
            if (r0 < PIN_ROWS) row_load_last(p, lane, w0);
            else               row_load_first(p, lane, w0);
        }
        if (v1) {
            const float* p = Wout + (long)r1 * H;
            if (r1 < PIN_ROWS) row_load_last(p, lane, w1);
            else               row_load_first(p, lane, w1);
        }
        float acc0 = v0 ? row_dot(w0, sx4, lane) : 0.f;
        float acc1 = v1 ? row_dot(w1, sx4, lane) : 0.f;
#pragma unroll
        for (int o = 16; o > 0; o >>= 1) {
            acc0 += __shfl_down_sync(0xffffffffu, acc0, o);
            acc1 += __shfl_down_sync(0xffffffffu, acc1, o);
        }
        if (lane == 0) {
            if (v0) {
                float v = acc0 + bout[r0];
                out[r0] = v;
                merge_pair(m, s, v, 1.0f);
            }
            if (v1) {
                float v = acc1 + bout[r1];
                out[r1] = v;
                merge_pair(m, s, v, 1.0f);
            }
        }
    }
    if (lane == 0) spair[warp] = make_float2(m, s);
    __syncthreads();
    if (t == 0) {
        float mm = spair[0].x, ss = spair[0].y;
#pragma unroll
        for (int wq = 1; wq < 16; wq++) merge_pair(mm, ss, spair[wq].x, spair[wq].y);
        g_pairs[blockIdx.x] = make_float2(mm, ss);
    }
    gsync(2);

    // P6: every block redundantly reduces g_pairs (identical order/bits),
    // then subtracts lse from its slice.
    {
        float mm = -INFINITY, ss = 0.f;
        if (t < NB) { float2 p = g_pairs[t]; mm = p.x; ss = p.y; }
#pragma unroll
        for (int o = 16; o > 0; o >>= 1) {
            float m2 = __shfl_down_sync(0xffffffffu, mm, o);
            float s2 = __shfl_down_sync(0xffffffffu, ss, o);
            merge_pair(mm, ss, m2, s2);
        }
        if (lane == 0 && warp < 5) spair[warp] = make_float2(mm, ss);
        __syncthreads();
        if (t == 0) {
            mm = spair[0].x; ss = spair[0].y;
#pragma unroll
            for (int wq = 1; wq < 5; wq++) merge_pair(mm, ss, spair[wq].x, spair[wq].y);
            s_lse = mm + logf(ss);
        }
        __syncthreads();
    }
    int i = blockIdx.x * FIN_CHUNK + t;
    if (t < FIN_CHUNK && i < VOCAB) out[i] -= s_lse;
}

// ---------------------------------------------------------------------------
extern "C" void kernel_launch(void* const* d_in, const int* in_sizes, int n_in,
                              void* d_out, int out_size) {
    const int*   id   = (const int*)d_in[0];
    const float* h0   = (const float*)d_in[1];
    const float* c0   = (const float*)d_in[2];
    const float* emb  = (const float*)d_in[3];
    const float* Wih  = (const float*)d_in[4];
    const float* Whh  = (const float*)d_in[5];
    const float* bih  = (const float*)d_in[6];
    const float* bhh  = (const float*)d_in[7];
    const float* Wout = (const float*)d_in[8];
    const float* bout = (const float*)d_in[9];
    float* out = (float*)d_out;

    int write_tail = (out_size >= VOCAB + 2 * H) ? 1 : 0;

    decoder_kernel<<<NB, NT>>>(id, h0, c0, emb, Wih, Whh, bih, bhh,
                               Wout, bout, out, write_tail);
}